// round 14
// baseline (speedup 1.0000x reference)
#include <cuda_runtime.h>
#include <cstdint>

#define NBLOCKS  591
#define NTHREADS 256
// 591 = 3*197 -> total = 151,296 threads divisible by 3 (chunk%3 per-thread const).
// 591 <= 592 = 4 CTAs/SM x 148 SMs at 256 threads -> 1024 thr/SM, single wave,
// 32 warps/SM for latency coverage. Register cap 64 via __launch_bounds__.

__device__ float        g_ptot[NBLOCKS];
__device__ float        g_prs[NBLOCKS];
__device__ unsigned int g_ctr = 0;   // reset by the last block each call

#define PI_F     3.14159265358979323846f
#define TPI_F    6.28318530717958647692f
#define INV2PI_F 0.15915494309189533577f
#define MAGIC_F  12582912.0f             // 1.5 * 2^23: RNE integer rounding

typedef unsigned long long u64;

// ---- packed f32x2 helpers (Blackwell) ----
__device__ __forceinline__ u64 pk2(float lo, float hi) {
    u64 r; asm("mov.b64 %0, {%1, %2};" : "=l"(r) : "f"(lo), "f"(hi)); return r;
}
__device__ __forceinline__ void unpk2(u64 v, float& lo, float& hi) {
    asm("mov.b64 {%0, %1}, %2;" : "=f"(lo), "=f"(hi) : "l"(v));
}
__device__ __forceinline__ u64 f2add(u64 a, u64 b) {
    u64 r; asm("add.rn.f32x2 %0, %1, %2;" : "=l"(r) : "l"(a), "l"(b)); return r;
}
__device__ __forceinline__ u64 f2mul(u64 a, u64 b) {
    u64 r; asm("mul.rn.f32x2 %0, %1, %2;" : "=l"(r) : "l"(a), "l"(b)); return r;
}
__device__ __forceinline__ u64 f2fma(u64 a, u64 b, u64 c) {
    u64 r; asm("fma.rn.f32x2 %0, %1, %2, %3;" : "=l"(r) : "l"(a), "l"(b), "l"(c));
    return r;
}

// scalar wrap (tail path only)
__device__ __forceinline__ float wrap_corr(float x) {
    return (fabsf(x) > PI_F) ? -copysignf(TPI_F, x) : 0.0f;
}

// Blackwell 256-bit global load: 8 consecutive floats per thread.
__device__ __forceinline__ void ldg256(const float* __restrict__ p, float* r) {
    asm("ld.global.nc.v8.f32 {%0,%1,%2,%3,%4,%5,%6,%7}, [%8];"
        : "=f"(r[0]), "=f"(r[1]), "=f"(r[2]), "=f"(r[3]),
          "=f"(r[4]), "=f"(r[5]), "=f"(r[6]), "=f"(r[7])
        : "l"(p));
}

struct PackedConsts {
    u64 inv2pi2, magic2, negmagic2, neg2pi2, negone2;
};

// wrapped(x) = fma(rint(x/2pi), -2pi, x); rint via magic-number RNE.
// Bit-identical to the reference's single +/-2pi wrap for |x| < 3pi.
__device__ __forceinline__ u64 wrap2(u64 x2, const PackedConsts& C) {
    u64 f = f2fma(x2, C.inv2pi2, C.magic2);   // low bits = rint(x/2pi)
    u64 r = f2add(f, C.negmagic2);            // exact integer (Sterbenz)
    return f2fma(r, C.neg2pi2, x2);           // x - 2pi*rint(x/2pi)
}

// 8 elements (4 packed pairs): only add/mul/fma.f32x2 — no compares/selects.
__device__ __forceinline__ void accum8p(const float* P, const float* T,
                                        const u64* wsel2, const PackedConsts& C,
                                        u64& tot2, u64& rs2) {
    #pragma unroll
    for (int j = 0; j < 4; j++) {
        u64 p2 = pk2(P[2*j], P[2*j+1]);
        u64 t2 = pk2(T[2*j], T[2*j+1]);
        u64 wp    = wrap2(p2, C);
        u64 wt    = wrap2(t2, C);
        u64 draw  = f2fma(t2, C.negone2, p2);     // p - t
        u64 dwrap = f2fma(wt, C.negone2, wp);     // wrap(p) - wrap(t)
        u64 diff  = f2fma(draw, C.negone2, dwrap);// dwrap - draw
        u64 v     = f2fma(wsel2[j], diff, draw);  // trans: draw, rot: dwrap
        u64 q     = f2mul(v, v);
        tot2 = f2add(tot2, q);
        rs2  = f2fma(q, wsel2[j], rs2);
    }
}

__global__ void __launch_bounds__(NTHREADS, 4)
wmse_kernel(const float* __restrict__ pf, const float* __restrict__ tf,
            unsigned n, float* __restrict__ out) {
    const unsigned total = NBLOCKS * NTHREADS;     // divisible by 3
    const unsigned tid   = blockIdx.x * NTHREADS + threadIdx.x;
    const unsigned n8    = n / 8u;                 // 8-float chunks

    PackedConsts C;
    C.inv2pi2   = pk2(INV2PI_F, INV2PI_F);
    C.magic2    = pk2(MAGIC_F, MAGIC_F);
    C.negmagic2 = pk2(-MAGIC_F, -MAGIC_F);
    C.neg2pi2   = pk2(-TPI_F, -TPI_F);
    C.negone2   = pk2(-1.0f, -1.0f);

    // Channels of chunk u: pattern depends only on u % 3 == tid % 3:
    //   m=0 -> rot lanes {3,4,5}; m=1 -> {1,2,3,7}; m=2 -> {0,1,5,6,7}
    const unsigned m = tid % 3u;
    float w[8];
    w[0] = (m == 2u) ? 1.0f : 0.0f;
    w[1] = (m != 0u) ? 1.0f : 0.0f;
    w[2] = (m == 1u) ? 1.0f : 0.0f;
    w[3] = (m != 2u) ? 1.0f : 0.0f;
    w[4] = (m == 0u) ? 1.0f : 0.0f;
    w[5] = (m != 1u) ? 1.0f : 0.0f;
    w[6] = (m == 2u) ? 1.0f : 0.0f;
    w[7] = (m != 0u) ? 1.0f : 0.0f;
    u64 wsel2[4];
    #pragma unroll
    for (int j = 0; j < 4; j++) wsel2[j] = pk2(w[2*j], w[2*j+1]);

    u64 tot2 = 0ull;   // packed (lo,hi) partial sums over ALL lanes
    u64 rs2  = 0ull;   // packed partial sums over rotation lanes

    // Two-buffer software-pipelined mainloop.
    float PA[8], TA[8], PB[8], TB[8];
    unsigned u = tid;
    if (u < n8) {
        ldg256(pf + (size_t)u * 8u, PA);
        ldg256(tf + (size_t)u * 8u, TA);
        for (;;) {
            unsigned u1 = u + total;
            if (u1 < n8) {
                ldg256(pf + (size_t)u1 * 8u, PB);
                ldg256(tf + (size_t)u1 * 8u, TB);
                accum8p(PA, TA, wsel2, C, tot2, rs2);
                unsigned u2 = u1 + total;
                if (u2 < n8) {
                    ldg256(pf + (size_t)u2 * 8u, PA);
                    ldg256(tf + (size_t)u2 * 8u, TA);
                    accum8p(PB, TB, wsel2, C, tot2, rs2);
                    u = u2;
                    continue;
                }
                accum8p(PB, TB, wsel2, C, tot2, rs2);
                break;
            }
            accum8p(PA, TA, wsel2, C, tot2, rs2);
            break;
        }
    }

    float tlo, thi, rlo, rhi;
    unpk2(tot2, tlo, thi);
    unpk2(rs2,  rlo, rhi);
    float tot = tlo + thi;
    float rs  = rlo + rhi;

    // Generic tail: floats beyond the last full 8-chunk (empty for bench shape).
    if (tid == 0) {
        for (unsigned f = n8 * 8u; f < n; f++) {
            unsigned c = f % 6u;
            float d  = pf[f] - tf[f];
            float cd = wrap_corr(pf[f]) - wrap_corr(tf[f]);
            float v  = (c >= 3u) ? (d + cd) : d;
            float q  = v * v;
            tot += q;
            if (c >= 3u) rs += q;
        }
    }

    // Block reduction of (tot, rs)
    #pragma unroll
    for (int o = 16; o > 0; o >>= 1) {
        tot += __shfl_xor_sync(0xffffffffu, tot, o);
        rs  += __shfl_xor_sync(0xffffffffu, rs, o);
    }
    __shared__ float stot[NTHREADS / 32];
    __shared__ float srs[NTHREADS / 32];
    int lane = threadIdx.x & 31;
    int warp = threadIdx.x >> 5;
    if (lane == 0) { stot[warp] = tot; srs[warp] = rs; }
    __syncthreads();

    __shared__ bool isLast;
    if (threadIdx.x == 0) {
        float btot = 0.0f, brs = 0.0f;
        #pragma unroll
        for (int ww = 0; ww < NTHREADS / 32; ww++) { btot += stot[ww]; brs += srs[ww]; }
        g_ptot[blockIdx.x] = btot;
        g_prs[blockIdx.x]  = brs;
        __threadfence();
        unsigned prev = atomicAdd(&g_ctr, 1u);
        isLast = (prev == (unsigned)gridDim.x - 1u);
    }
    __syncthreads();

    if (isLast) {
        __threadfence();
        float a = 0.0f, b = 0.0f;
        for (unsigned i = threadIdx.x; i < NBLOCKS; i += NTHREADS) {
            a += g_ptot[i];
            b += g_prs[i];
        }
        #pragma unroll
        for (int o = 16; o > 0; o >>= 1) {
            a += __shfl_xor_sync(0xffffffffu, a, o);
            b += __shfl_xor_sync(0xffffffffu, b, o);
        }
        __syncthreads();                 // stot/srs reuse
        if (lane == 0) { stot[warp] = a; srs[warp] = b; }
        __syncthreads();
        if (threadIdx.x == 0) {
            float A = 0.0f, B = 0.0f;    // A = tot sum, B = rot sum
            #pragma unroll
            for (int ww = 0; ww < NTHREADS / 32; ww++) { A += stot[ww]; B += srs[ww]; }
            g_ctr = 0;                   // rearm for the next graph replay
            double cnt        = (double)n * 0.5;             // elems / 2
            double rot_sum    = (double)B;
            double trans_sum  = (double)A - rot_sum;         // tot - rot
            double trans_loss = trans_sum / cnt;             // TRANS_WEIGHT=1
            double rot_loss   = (rot_sum / cnt) * 100.0;     // ROT_WEIGHT=100
            out[0] = (float)(trans_loss + rot_loss);
            out[1] = (float)trans_loss;
            out[2] = (float)rot_loss;
        }
    }
}

extern "C" void kernel_launch(void* const* d_in, const int* in_sizes, int n_in,
                              void* d_out, int out_size) {
    const float* pred   = (const float*)d_in[0];
    const float* target = (const float*)d_in[1];
    unsigned n = (unsigned)in_sizes[0];

    wmse_kernel<<<NBLOCKS, NTHREADS>>>(pred, target, n, (float*)d_out);
}

// round 16
// speedup vs baseline: 1.0009x; 1.0009x over previous
#include <cuda_runtime.h>
#include <cstdint>

#define NBLOCKS  296
#define NTHREADS 384
// 296 = 2 CTAs/SM x 148 SMs at 384 threads -> 768 thr/SM (R13-proven optimum).
// total = 113,664 threads, divisible by 3 -> chunk%3 loop-invariant per thread.

__device__ float        g_ptot[NBLOCKS];
__device__ float        g_prs[NBLOCKS];
__device__ unsigned int g_ctr = 0;   // reset by the last block each call

#define PI_F     3.14159265358979323846f
#define TPI_F    6.28318530717958647692f
#define INV2PI_F 0.15915494309189533577f
#define MAGIC_F  12582912.0f             // 1.5 * 2^23: RNE integer rounding

typedef unsigned long long u64;

// ---- packed f32x2 helpers (Blackwell) ----
__device__ __forceinline__ u64 pk2(float lo, float hi) {
    u64 r; asm("mov.b64 %0, {%1, %2};" : "=l"(r) : "f"(lo), "f"(hi)); return r;
}
__device__ __forceinline__ void unpk2(u64 v, float& lo, float& hi) {
    asm("mov.b64 {%0, %1}, %2;" : "=f"(lo), "=f"(hi) : "l"(v));
}
__device__ __forceinline__ u64 f2add(u64 a, u64 b) {
    u64 r; asm("add.rn.f32x2 %0, %1, %2;" : "=l"(r) : "l"(a), "l"(b)); return r;
}
__device__ __forceinline__ u64 f2mul(u64 a, u64 b) {
    u64 r; asm("mul.rn.f32x2 %0, %1, %2;" : "=l"(r) : "l"(a), "l"(b)); return r;
}
__device__ __forceinline__ u64 f2fma(u64 a, u64 b, u64 c) {
    u64 r; asm("fma.rn.f32x2 %0, %1, %2, %3;" : "=l"(r) : "l"(a), "l"(b), "l"(c));
    return r;
}

// scalar wrap (tail path only)
__device__ __forceinline__ float wrap_corr(float x) {
    return (fabsf(x) > PI_F) ? -copysignf(TPI_F, x) : 0.0f;
}

// Blackwell 256-bit global load: 8 consecutive floats per thread.
__device__ __forceinline__ void ldg256(const float* __restrict__ p, float* r) {
    asm("ld.global.nc.v8.f32 {%0,%1,%2,%3,%4,%5,%6,%7}, [%8];"
        : "=f"(r[0]), "=f"(r[1]), "=f"(r[2]), "=f"(r[3]),
          "=f"(r[4]), "=f"(r[5]), "=f"(r[6]), "=f"(r[7])
        : "l"(p));
}

struct PackedConsts {
    u64 inv2pi2, magic2, negone2;
};

// 8 elements (4 packed pairs), 8 packed ops per pair:
//   f_p = fma(p, 1/2pi, magic)  -> equals magic + rint(p/2pi) EXACTLY (RNE)
//   f_t likewise; f_t - f_p = r_t - r_p exactly.
//   v   = fma(w*2pi, f_t - f_p, p - t)
//       = (p - t)                 on trans lanes (w = 0)
//       = wrap(p) - wrap(t)       on rot lanes   (w = 1)
__device__ __forceinline__ void accum8p(const float* P, const float* T,
                                        const u64* wsel2, const u64* w2pi2,
                                        const PackedConsts& C,
                                        u64& tot2, u64& rs2) {
    #pragma unroll
    for (int j = 0; j < 4; j++) {
        u64 p2 = pk2(P[2*j], P[2*j+1]);
        u64 t2 = pk2(T[2*j], T[2*j+1]);
        u64 fp   = f2fma(p2, C.inv2pi2, C.magic2);
        u64 ft   = f2fma(t2, C.inv2pi2, C.magic2);
        u64 draw = f2fma(t2, C.negone2, p2);     // p - t
        u64 fd   = f2fma(fp, C.negone2, ft);     // r_t - r_p (exact)
        u64 v    = f2fma(w2pi2[j], fd, draw);    // per-lane selected diff
        u64 q    = f2mul(v, v);
        tot2 = f2add(tot2, q);
        rs2  = f2fma(q, wsel2[j], rs2);
    }
}

__global__ void __launch_bounds__(NTHREADS, 2)
wmse_kernel(const float* __restrict__ pf, const float* __restrict__ tf,
            unsigned n, float* __restrict__ out) {
    const unsigned total = NBLOCKS * NTHREADS;     // divisible by 3
    const unsigned tid   = blockIdx.x * NTHREADS + threadIdx.x;
    const unsigned n8    = n / 8u;                 // 8-float chunks

    PackedConsts C;
    C.inv2pi2 = pk2(INV2PI_F, INV2PI_F);
    C.magic2  = pk2(MAGIC_F, MAGIC_F);
    C.negone2 = pk2(-1.0f, -1.0f);

    // Channels of chunk u: pattern depends only on u % 3 == tid % 3:
    //   m=0 -> rot lanes {3,4,5}; m=1 -> {1,2,3,7}; m=2 -> {0,1,5,6,7}
    const unsigned m = tid % 3u;
    float w[8];
    w[0] = (m == 2u) ? 1.0f : 0.0f;
    w[1] = (m != 0u) ? 1.0f : 0.0f;
    w[2] = (m == 1u) ? 1.0f : 0.0f;
    w[3] = (m != 2u) ? 1.0f : 0.0f;
    w[4] = (m == 0u) ? 1.0f : 0.0f;
    w[5] = (m != 1u) ? 1.0f : 0.0f;
    w[6] = (m == 2u) ? 1.0f : 0.0f;
    w[7] = (m != 0u) ? 1.0f : 0.0f;
    u64 wsel2[4], w2pi2[4];
    #pragma unroll
    for (int j = 0; j < 4; j++) {
        wsel2[j] = pk2(w[2*j], w[2*j+1]);
        w2pi2[j] = pk2(w[2*j] * TPI_F, w[2*j+1] * TPI_F);
    }

    u64 tot2 = 0ull;   // packed (lo,hi) partial sums over ALL lanes
    u64 rs2  = 0ull;   // packed partial sums over rotation lanes

    // Two-buffer software-pipelined mainloop (R11/R13-proven structure).
    float PA[8], TA[8], PB[8], TB[8];
    unsigned u = tid;
    if (u < n8) {
        ldg256(pf + (size_t)u * 8u, PA);
        ldg256(tf + (size_t)u * 8u, TA);
        for (;;) {
            unsigned u1 = u + total;
            if (u1 < n8) {
                ldg256(pf + (size_t)u1 * 8u, PB);
                ldg256(tf + (size_t)u1 * 8u, TB);
                accum8p(PA, TA, wsel2, w2pi2, C, tot2, rs2);
                unsigned u2 = u1 + total;
                if (u2 < n8) {
                    ldg256(pf + (size_t)u2 * 8u, PA);
                    ldg256(tf + (size_t)u2 * 8u, TA);
                    accum8p(PB, TB, wsel2, w2pi2, C, tot2, rs2);
                    u = u2;
                    continue;
                }
                accum8p(PB, TB, wsel2, w2pi2, C, tot2, rs2);
                break;
            }
            accum8p(PA, TA, wsel2, w2pi2, C, tot2, rs2);
            break;
        }
    }

    float tlo, thi, rlo, rhi;
    unpk2(tot2, tlo, thi);
    unpk2(rs2,  rlo, rhi);
    float tot = tlo + thi;
    float rs  = rlo + rhi;

    // Generic tail: floats beyond the last full 8-chunk (empty for bench shape).
    if (tid == 0) {
        for (unsigned f = n8 * 8u; f < n; f++) {
            unsigned c = f % 6u;
            float d  = pf[f] - tf[f];
            float cd = wrap_corr(pf[f]) - wrap_corr(tf[f]);
            float v  = (c >= 3u) ? (d + cd) : d;
            float q  = v * v;
            tot += q;
            if (c >= 3u) rs += q;
        }
    }

    // Block reduction of (tot, rs)
    #pragma unroll
    for (int o = 16; o > 0; o >>= 1) {
        tot += __shfl_xor_sync(0xffffffffu, tot, o);
        rs  += __shfl_xor_sync(0xffffffffu, rs, o);
    }
    __shared__ float stot[NTHREADS / 32];
    __shared__ float srs[NTHREADS / 32];
    int lane = threadIdx.x & 31;
    int warp = threadIdx.x >> 5;
    if (lane == 0) { stot[warp] = tot; srs[warp] = rs; }
    __syncthreads();

    __shared__ bool isLast;
    if (threadIdx.x == 0) {
        float btot = 0.0f, brs = 0.0f;
        #pragma unroll
        for (int ww = 0; ww < NTHREADS / 32; ww++) { btot += stot[ww]; brs += srs[ww]; }
        g_ptot[blockIdx.x] = btot;
        g_prs[blockIdx.x]  = brs;
        __threadfence();
        unsigned prev = atomicAdd(&g_ctr, 1u);
        isLast = (prev == (unsigned)gridDim.x - 1u);
    }
    __syncthreads();

    if (isLast) {
        __threadfence();
        float a = 0.0f, b = 0.0f;
        for (unsigned i = threadIdx.x; i < NBLOCKS; i += NTHREADS) {
            a += g_ptot[i];
            b += g_prs[i];
        }
        #pragma unroll
        for (int o = 16; o > 0; o >>= 1) {
            a += __shfl_xor_sync(0xffffffffu, a, o);
            b += __shfl_xor_sync(0xffffffffu, b, o);
        }
        __syncthreads();                 // stot/srs reuse
        if (lane == 0) { stot[warp] = a; srs[warp] = b; }
        __syncthreads();
        if (threadIdx.x == 0) {
            float A = 0.0f, B = 0.0f;    // A = tot sum, B = rot sum
            #pragma unroll
            for (int ww = 0; ww < NTHREADS / 32; ww++) { A += stot[ww]; B += srs[ww]; }
            g_ctr = 0;                   // rearm for the next graph replay
            double cnt        = (double)n * 0.5;             // elems / 2
            double rot_sum    = (double)B;
            double trans_sum  = (double)A - rot_sum;         // tot - rot
            double trans_loss = trans_sum / cnt;             // TRANS_WEIGHT=1
            double rot_loss   = (rot_sum / cnt) * 100.0;     // ROT_WEIGHT=100
            out[0] = (float)(trans_loss + rot_loss);
            out[1] = (float)trans_loss;
            out[2] = (float)rot_loss;
        }
    }
}

extern "C" void kernel_launch(void* const* d_in, const int* in_sizes, int n_in,
                              void* d_out, int out_size) {
    const float* pred   = (const float*)d_in[0];
    const float* target = (const float*)d_in[1];
    unsigned n = (unsigned)in_sizes[0];

    wmse_kernel<<<NBLOCKS, NTHREADS>>>(pred, target, n, (float*)d_out);
}

// round 17
// speedup vs baseline: 1.0079x; 1.0070x over previous
#include <cuda_runtime.h>
#include <cstdint>

#define NBLOCKS  296
#define NTHREADS 384
// 296 = 2 CTAs/SM x 148 SMs at 384 threads -> 768 thr/SM (R13-proven optimum).
// total = 113,664 threads, divisible by 3 -> chunk%3 loop-invariant per thread.

__device__ float        g_ptot[NBLOCKS];
__device__ float        g_prs[NBLOCKS];
__device__ unsigned int g_ctr = 0;   // reset by the last block each call

#define PI_F     3.14159265358979323846f
#define TPI_F    6.28318530717958647692f
#define INV2PI_F 0.15915494309189533577f
#define MAGIC_F  12582912.0f             // 1.5 * 2^23: RNE integer rounding

typedef unsigned long long u64;

// ---- packed f32x2 helpers (Blackwell) ----
__device__ __forceinline__ u64 pk2(float lo, float hi) {
    u64 r; asm("mov.b64 %0, {%1, %2};" : "=l"(r) : "f"(lo), "f"(hi)); return r;
}
__device__ __forceinline__ void unpk2(u64 v, float& lo, float& hi) {
    asm("mov.b64 {%0, %1}, %2;" : "=f"(lo), "=f"(hi) : "l"(v));
}
__device__ __forceinline__ u64 f2add(u64 a, u64 b) {
    u64 r; asm("add.rn.f32x2 %0, %1, %2;" : "=l"(r) : "l"(a), "l"(b)); return r;
}
__device__ __forceinline__ u64 f2mul(u64 a, u64 b) {
    u64 r; asm("mul.rn.f32x2 %0, %1, %2;" : "=l"(r) : "l"(a), "l"(b)); return r;
}
__device__ __forceinline__ u64 f2fma(u64 a, u64 b, u64 c) {
    u64 r; asm("fma.rn.f32x2 %0, %1, %2, %3;" : "=l"(r) : "l"(a), "l"(b), "l"(c));
    return r;
}

// scalar wrap (tail path only)
__device__ __forceinline__ float wrap_corr(float x) {
    return (fabsf(x) > PI_F) ? -copysignf(TPI_F, x) : 0.0f;
}

// Blackwell 256-bit global load, streaming (L2 evict-first: read-once data).
__device__ __forceinline__ void ldg256s(const float* __restrict__ p, float* r) {
    asm("ld.global.nc.L2::evict_first.v8.f32 {%0,%1,%2,%3,%4,%5,%6,%7}, [%8];"
        : "=f"(r[0]), "=f"(r[1]), "=f"(r[2]), "=f"(r[3]),
          "=f"(r[4]), "=f"(r[5]), "=f"(r[6]), "=f"(r[7])
        : "l"(p));
}

struct PackedConsts {
    u64 inv2pi2, magic2, negone2;
};

// 8 elements (4 packed pairs), 8 packed ops per pair:
//   f_p = fma(p, 1/2pi, magic) == magic + rint(p/2pi) EXACTLY (RNE);
//   f_t - f_p = r_t - r_p exactly (magic cancels).
//   v = fma(w*2pi, f_t - f_p, p - t): trans lanes (w=0) -> p-t,
//                                     rot lanes (w=1) -> wrap(p)-wrap(t).
__device__ __forceinline__ void accum8p(const float* P, const float* T,
                                        const u64* wsel2, const u64* w2pi2,
                                        const PackedConsts& C,
                                        u64& tot2, u64& rs2) {
    #pragma unroll
    for (int j = 0; j < 4; j++) {
        u64 p2 = pk2(P[2*j], P[2*j+1]);
        u64 t2 = pk2(T[2*j], T[2*j+1]);
        u64 fp   = f2fma(p2, C.inv2pi2, C.magic2);
        u64 ft   = f2fma(t2, C.inv2pi2, C.magic2);
        u64 draw = f2fma(t2, C.negone2, p2);     // p - t
        u64 fd   = f2fma(fp, C.negone2, ft);     // r_t - r_p (exact)
        u64 v    = f2fma(w2pi2[j], fd, draw);    // per-lane selected diff
        u64 q    = f2mul(v, v);
        tot2 = f2add(tot2, q);
        rs2  = f2fma(q, wsel2[j], rs2);
    }
}

__global__ void __launch_bounds__(NTHREADS, 2)
wmse_kernel(const float* __restrict__ pf, const float* __restrict__ tf,
            unsigned n, float* __restrict__ out) {
    const unsigned total = NBLOCKS * NTHREADS;     // divisible by 3
    const unsigned tid   = blockIdx.x * NTHREADS + threadIdx.x;
    const unsigned n8    = n / 8u;                 // 8-float chunks

    PackedConsts C;
    C.inv2pi2 = pk2(INV2PI_F, INV2PI_F);
    C.magic2  = pk2(MAGIC_F, MAGIC_F);
    C.negone2 = pk2(-1.0f, -1.0f);

    // Channels of chunk u: pattern depends only on u % 3 == tid % 3:
    //   m=0 -> rot lanes {3,4,5}; m=1 -> {1,2,3,7}; m=2 -> {0,1,5,6,7}
    const unsigned m = tid % 3u;
    float w[8];
    w[0] = (m == 2u) ? 1.0f : 0.0f;
    w[1] = (m != 0u) ? 1.0f : 0.0f;
    w[2] = (m == 1u) ? 1.0f : 0.0f;
    w[3] = (m != 2u) ? 1.0f : 0.0f;
    w[4] = (m == 0u) ? 1.0f : 0.0f;
    w[5] = (m != 1u) ? 1.0f : 0.0f;
    w[6] = (m == 2u) ? 1.0f : 0.0f;
    w[7] = (m != 0u) ? 1.0f : 0.0f;
    u64 wsel2[4], w2pi2[4];
    #pragma unroll
    for (int j = 0; j < 4; j++) {
        wsel2[j] = pk2(w[2*j], w[2*j+1]);
        w2pi2[j] = pk2(w[2*j] * TPI_F, w[2*j+1] * TPI_F);
    }

    u64 tot2 = 0ull;   // packed (lo,hi) partial sums over ALL lanes
    u64 rs2  = 0ull;   // packed partial sums over rotation lanes

    // Uniform-trip-count two-buffer pipeline: every thread does `iters` full
    // chunks with no bounds checks; the ragged +1 chunk goes in the epilogue.
    const unsigned iters = n8 / total;             // 27 for the bench shape
    float PA[8], TA[8], PB[8], TB[8];
    unsigned u = tid;

    if (iters >= 1u) {
        ldg256s(pf + (size_t)u * 8u, PA);
        ldg256s(tf + (size_t)u * 8u, TA);
        unsigned k = 1u;
        for (; k + 1u < iters; k += 2u) {
            ldg256s(pf + (size_t)(u + total) * 8u, PB);
            ldg256s(tf + (size_t)(u + total) * 8u, TB);
            accum8p(PA, TA, wsel2, w2pi2, C, tot2, rs2);
            ldg256s(pf + (size_t)(u + 2u * total) * 8u, PA);
            ldg256s(tf + (size_t)(u + 2u * total) * 8u, TA);
            accum8p(PB, TB, wsel2, w2pi2, C, tot2, rs2);
            u += 2u * total;
        }
        if (k < iters) {   // one more full chunk (iters even w.r.t. loop exit)
            ldg256s(pf + (size_t)(u + total) * 8u, PB);
            ldg256s(tf + (size_t)(u + total) * 8u, TB);
            accum8p(PA, TA, wsel2, w2pi2, C, tot2, rs2);
            accum8p(PB, TB, wsel2, w2pi2, C, tot2, rs2);
            u += total;
        } else {
            accum8p(PA, TA, wsel2, w2pi2, C, tot2, rs2);
        }
        u += total;
    }
    // Ragged extra chunk for threads with tid < n8 % total.
    if (u < n8) {
        ldg256s(pf + (size_t)u * 8u, PA);
        ldg256s(tf + (size_t)u * 8u, TA);
        accum8p(PA, TA, wsel2, w2pi2, C, tot2, rs2);
    }

    float tlo, thi, rlo, rhi;
    unpk2(tot2, tlo, thi);
    unpk2(rs2,  rlo, rhi);
    float tot = tlo + thi;
    float rs  = rlo + rhi;

    // Generic tail: floats beyond the last full 8-chunk (empty for bench shape).
    if (tid == 0) {
        for (unsigned f = n8 * 8u; f < n; f++) {
            unsigned c = f % 6u;
            float d  = pf[f] - tf[f];
            float cd = wrap_corr(pf[f]) - wrap_corr(tf[f]);
            float v  = (c >= 3u) ? (d + cd) : d;
            float q  = v * v;
            tot += q;
            if (c >= 3u) rs += q;
        }
    }

    // Block reduction of (tot, rs)
    #pragma unroll
    for (int o = 16; o > 0; o >>= 1) {
        tot += __shfl_xor_sync(0xffffffffu, tot, o);
        rs  += __shfl_xor_sync(0xffffffffu, rs, o);
    }
    __shared__ float stot[NTHREADS / 32];
    __shared__ float srs[NTHREADS / 32];
    int lane = threadIdx.x & 31;
    int warp = threadIdx.x >> 5;
    if (lane == 0) { stot[warp] = tot; srs[warp] = rs; }
    __syncthreads();

    __shared__ bool isLast;
    if (threadIdx.x == 0) {
        float btot = 0.0f, brs = 0.0f;
        #pragma unroll
        for (int ww = 0; ww < NTHREADS / 32; ww++) { btot += stot[ww]; brs += srs[ww]; }
        g_ptot[blockIdx.x] = btot;
        g_prs[blockIdx.x]  = brs;
        __threadfence();
        unsigned prev = atomicAdd(&g_ctr, 1u);
        isLast = (prev == (unsigned)gridDim.x - 1u);
    }
    __syncthreads();

    if (isLast) {
        __threadfence();
        float a = 0.0f, b = 0.0f;
        for (unsigned i = threadIdx.x; i < NBLOCKS; i += NTHREADS) {
            a += g_ptot[i];
            b += g_prs[i];
        }
        #pragma unroll
        for (int o = 16; o > 0; o >>= 1) {
            a += __shfl_xor_sync(0xffffffffu, a, o);
            b += __shfl_xor_sync(0xffffffffu, b, o);
        }
        __syncthreads();                 // stot/srs reuse
        if (lane == 0) { stot[warp] = a; srs[warp] = b; }
        __syncthreads();
        if (threadIdx.x == 0) {
            float A = 0.0f, B = 0.0f;    // A = tot sum, B = rot sum
            #pragma unroll
            for (int ww = 0; ww < NTHREADS / 32; ww++) { A += stot[ww]; B += srs[ww]; }
            g_ctr = 0;                   // rearm for the next graph replay
            double cnt        = (double)n * 0.5;             // elems / 2
            double rot_sum    = (double)B;
            double trans_sum  = (double)A - rot_sum;         // tot - rot
            double trans_loss = trans_sum / cnt;             // TRANS_WEIGHT=1
            double rot_loss   = (rot_sum / cnt) * 100.0;     // ROT_WEIGHT=100
            out[0] = (float)(trans_loss + rot_loss);
            out[1] = (float)trans_loss;
            out[2] = (float)rot_loss;
        }
    }
}

extern "C" void kernel_launch(void* const* d_in, const int* in_sizes, int n_in,
                              void* d_out, int out_size) {
    const float* pred   = (const float*)d_in[0];
    const float* target = (const float*)d_in[1];
    unsigned n = (unsigned)in_sizes[0];

    wmse_kernel<<<NBLOCKS, NTHREADS>>>(pred, target, n, (float*)d_out);
}